// round 13
// baseline (speedup 1.0000x reference)
#include <cuda_runtime.h>
#include <cuda_bf16.h>

#define NPTS   65536
#define CHN    256
#define BATCH  16
#define LOUT   8192
#define LOG2L  13

// g_off[b] = first index with batch id >= b; g_off[BATCH] = NPTS.
__device__ int g_off[BATCH + 1];
__device__ int g_flag;   // 0 -> boundaries not ready; 1 -> ready (sticky across
                         // replays; block 0 rewrites identical values, benign)

// ----------------------------------------------------------- single kernel -
// blocks [0, PT_BLOCKS): points. blocks [PT_BLOCKS, PT_BLOCKS+8192): features
// (R8 body: endpoint-dedup loads, 512B warp-contiguous STG.128).
// Block 0 computes g_off via warp-cooperative 32-ary lower_bound (~1us) and
// releases g_flag; other blocks spin on it with one thread (first wave only).
#define PT_BLOCKS 128

__global__ __launch_bounds__(256)
void gather_kernel(const float* __restrict__ px,
                   const float4* __restrict__ feat4,
                   const int* __restrict__ batch,
                   float* __restrict__ out_point,
                   float* __restrict__ out_feat) {
    __shared__ int s_off, s_cnt;
    int bid = blockIdx.x;
    int tid = threadIdx.x;

    if (bid == 0) {
        // ---- compute boundaries: 8 warps, 2 passes, keys 1..15.
        int w = tid >> 5, L = tid & 31;
        #pragma unroll
        for (int pass = 0; pass < 2; pass++) {
            int key = 1 + w + pass * 8;
            if (key <= 15) {
                int lo = -1;
                int s = 2048;                 // 65536 -> 2048 -> 64 -> 2
                #pragma unroll
                for (int lev = 0; lev < 3; lev++) {
                    int pos = lo + (L + 1) * s;
                    int val = (pos < NPTS) ? __ldg(&batch[pos]) : 0x7fffffff;
                    unsigned m = __ballot_sync(0xffffffffu, val < key);
                    lo += __popc(m) * s;
                    s >>= 5;
                }
                bool pred = false;
                if (L < 2) {
                    int pos = lo + 1 + L;
                    pred = (pos < NPTS) && (__ldg(&batch[pos]) < key);
                }
                unsigned m = __ballot_sync(0xffffffffu, pred);
                if (L == 0) g_off[key] = lo + 1 + __popc(m);
            }
        }
        if (tid == 0) { g_off[0] = 0; g_off[BATCH] = NPTS; }
        __syncthreads();
        if (tid == 0) {
            __threadfence();
            *(volatile int*)&g_flag = 1;
        }
        // falls through to its own (points, b=0) work; g_off valid here.
    } else {
        if (tid == 0) {
            while (*(volatile int*)&g_flag == 0) { }
            __threadfence();                  // acquire
        }
        __syncthreads();
    }

    if (bid < PT_BLOCKS) {
        // ---- points: thread = 4 consecutive j; float4 writes.
        int idx = bid * 256 + tid;            // 0..32767
        int b = idx >> 11;
        int j = (idx & 2047) * 4;
        if (tid == 0) { s_off = g_off[b]; s_cnt = g_off[b + 1] - g_off[b]; }
        __syncthreads();
        int off = s_off, cnt = s_cnt;
        float4 ox, oy, oz;
        #pragma unroll
        for (int t = 0; t < 4; t++) {
            int src = off + (int)(((unsigned)((j + t) * cnt)) >> LOG2L);
            const float* p = px + 3 * src;
            ((float*)&ox)[t] = p[0];
            ((float*)&oy)[t] = p[1];
            ((float*)&oz)[t] = p[2];
        }
        size_t base = (size_t)b * 3 * LOUT + j;
        __stcs((float4*)(out_point + base),            ox);
        __stcs((float4*)(out_point + base + LOUT),     oy);
        __stcs((float4*)(out_point + base + 2 * LOUT), oz);
        return;
    }

    // ---- features (R8 body) ----
    int idx = (bid - PT_BLOCKS) * 256 + tid;  // 0 .. 2097151
    int jq = idx & 2047;
    int c4 = (idx >> 11) & 63;
    int b  = idx >> 17;                       // block-uniform
    int j0 = jq * 4;
    if (tid == 0) { s_off = g_off[b]; s_cnt = g_off[b + 1] - g_off[b]; }
    __syncthreads();
    int off = s_off, cnt = s_cnt;

    // Monotone source rows; load endpoints, select/rare-load interiors.
    int r0 = off + (int)(((unsigned)((j0 + 0) * cnt)) >> LOG2L);
    int r1 = off + (int)(((unsigned)((j0 + 1) * cnt)) >> LOG2L);
    int r2 = off + (int)(((unsigned)((j0 + 2) * cnt)) >> LOG2L);
    int r3 = off + (int)(((unsigned)((j0 + 3) * cnt)) >> LOG2L);

    const float4* fb = feat4 + c4;
    float4 A = __ldg(fb + (size_t)r0 * (CHN / 4));
    float4 D = __ldg(fb + (size_t)r3 * (CHN / 4));
    float4 v1 = (r1 == r0) ? A : D;
    if (r1 > r0 && r1 < r3) v1 = __ldg(fb + (size_t)r1 * (CHN / 4));
    float4 v2 = (r2 == r3) ? D : A;
    if (r2 > r0 && r2 < r3) v2 = __ldg(fb + (size_t)r2 * (CHN / 4));

    float* ob = out_feat + ((size_t)b * CHN + 4 * c4) * LOUT + j0;
    float4 o;
    o.x = A.x;  o.y = v1.x; o.z = v2.x; o.w = D.x;
    __stcs((float4*)(ob + 0 * LOUT), o);
    o.x = A.y;  o.y = v1.y; o.z = v2.y; o.w = D.y;
    __stcs((float4*)(ob + 1 * LOUT), o);
    o.x = A.z;  o.y = v1.z; o.z = v2.z; o.w = D.z;
    __stcs((float4*)(ob + 2 * LOUT), o);
    o.x = A.w;  o.y = v1.w; o.z = v2.w; o.w = D.w;
    __stcs((float4*)(ob + 3 * LOUT), o);
}

// ------------------------------------------------------------- launch ------
extern "C" void kernel_launch(void* const* d_in, const int* in_sizes, int n_in,
                              void* d_out, int out_size) {
    const float* points_x = (const float*)d_in[0];   // [N,3]
    const float* feat     = (const float*)d_in[1];   // [N,C]
    const int*   batch    = (const int*)d_in[2];     // [N]

    float* out_point = (float*)d_out;                              // [B,3,L]
    float* out_feat  = (float*)d_out + (size_t)BATCH * 3 * LOUT;   // [B,C,L]

    gather_kernel<<<PT_BLOCKS + 8192, 256>>>(points_x, (const float4*)feat,
                                             batch, out_point, out_feat);
}

// round 14
// speedup vs baseline: 1.1235x; 1.1235x over previous
#include <cuda_runtime.h>
#include <cuda_bf16.h>

#define NPTS   65536
#define CHN    256
#define BATCH  16
#define LOUT   8192
#define LOG2L  13

// g_off[b] = first index with batch id >= b; g_off[BATCH] = NPTS.
__device__ int g_off[BATCH + 1];

// ------------------------------------------------------- boundary detect ---
// batch sorted; int4 loads, boundary write-out, no atomics. PDL trigger at
// entry so the gather grid launches while this runs.
__global__ void boundary_kernel(const int* __restrict__ batch) {
    asm volatile("griddepcontrol.launch_dependents;");
    int t = blockIdx.x * blockDim.x + threadIdx.x;   // 0 .. NPTS/4-1
    if (t >= NPTS / 4) return;
    int4 v = ((const int4*)batch)[t];
    int prev = (t == 0) ? -1 : __ldg(&batch[4 * t - 1]);
    for (int bb = prev + 1; bb <= v.x; bb++) g_off[bb] = 4 * t + 0;
    for (int bb = v.x + 1;  bb <= v.y; bb++) g_off[bb] = 4 * t + 1;
    for (int bb = v.y + 1;  bb <= v.z; bb++) g_off[bb] = 4 * t + 2;
    for (int bb = v.z + 1;  bb <= v.w; bb++) g_off[bb] = 4 * t + 3;
    if (t == NPTS / 4 - 1)
        for (int bb = v.w + 1; bb <= BATCH; bb++) g_off[bb] = NPTS;
}

// ----------------------------------------------------------- main gather ---
// R8 body (best measured: 37.5us, ~96% of the 3.86TB/s write-drain floor).
// __launch_bounds__(256, 8) to force regs<=32 -> 8 resident blocks/SM.
#define PT_BLOCKS 128

__global__ __launch_bounds__(256, 8)
void gather_kernel(const float* __restrict__ px,
                   const float4* __restrict__ feat4,
                   float* __restrict__ out_point,
                   float* __restrict__ out_feat) {
    __shared__ int s_off, s_cnt;
    int bid = blockIdx.x;
    int tid = threadIdx.x;

    if (bid < PT_BLOCKS) {
        int idx = bid * 256 + tid;            // 0..32767
        int b = idx >> 11;
        int j = (idx & 2047) * 4;
        asm volatile("griddepcontrol.wait;");
        if (tid == 0) { s_off = g_off[b]; s_cnt = g_off[b + 1] - g_off[b]; }
        __syncthreads();
        int off = s_off, cnt = s_cnt;
        float4 ox, oy, oz;
        #pragma unroll
        for (int t = 0; t < 4; t++) {
            int src = off + (int)(((unsigned)((j + t) * cnt)) >> LOG2L);
            const float* p = px + 3 * src;
            ((float*)&ox)[t] = p[0];
            ((float*)&oy)[t] = p[1];
            ((float*)&oz)[t] = p[2];
        }
        size_t base = (size_t)b * 3 * LOUT + j;
        __stcs((float4*)(out_point + base),            ox);
        __stcs((float4*)(out_point + base + LOUT),     oy);
        __stcs((float4*)(out_point + base + 2 * LOUT), oz);
        return;
    }

    // ---- features ----
    int idx = (bid - PT_BLOCKS) * 256 + tid;  // 0 .. 2097151
    int jq = idx & 2047;
    int c4 = (idx >> 11) & 63;
    int b  = idx >> 17;                       // block-uniform
    int j0 = jq * 4;
    asm volatile("griddepcontrol.wait;");
    if (tid == 0) { s_off = g_off[b]; s_cnt = g_off[b + 1] - g_off[b]; }
    __syncthreads();
    int off = s_off, cnt = s_cnt;

    // Monotone source rows; load endpoints, select/rare-load interiors.
    int r0 = off + (int)(((unsigned)((j0 + 0) * cnt)) >> LOG2L);
    int r1 = off + (int)(((unsigned)((j0 + 1) * cnt)) >> LOG2L);
    int r2 = off + (int)(((unsigned)((j0 + 2) * cnt)) >> LOG2L);
    int r3 = off + (int)(((unsigned)((j0 + 3) * cnt)) >> LOG2L);

    const float4* fb = feat4 + c4;
    float4 A = __ldg(fb + (size_t)r0 * (CHN / 4));
    float4 D = __ldg(fb + (size_t)r3 * (CHN / 4));
    float4 v1 = (r1 == r0) ? A : D;
    if (r1 > r0 && r1 < r3) v1 = __ldg(fb + (size_t)r1 * (CHN / 4));
    float4 v2 = (r2 == r3) ? D : A;
    if (r2 > r0 && r2 < r3) v2 = __ldg(fb + (size_t)r2 * (CHN / 4));

    float* ob = out_feat + ((size_t)b * CHN + 4 * c4) * LOUT + j0;
    float4 o;
    o.x = A.x;  o.y = v1.x; o.z = v2.x; o.w = D.x;
    __stcs((float4*)(ob + 0 * LOUT), o);
    o.x = A.y;  o.y = v1.y; o.z = v2.y; o.w = D.y;
    __stcs((float4*)(ob + 1 * LOUT), o);
    o.x = A.z;  o.y = v1.z; o.z = v2.z; o.w = D.z;
    __stcs((float4*)(ob + 2 * LOUT), o);
    o.x = A.w;  o.y = v1.w; o.z = v2.w; o.w = D.w;
    __stcs((float4*)(ob + 3 * LOUT), o);
}

// ------------------------------------------------------------- launch ------
extern "C" void kernel_launch(void* const* d_in, const int* in_sizes, int n_in,
                              void* d_out, int out_size) {
    const float* points_x = (const float*)d_in[0];   // [N,3]
    const float* feat     = (const float*)d_in[1];   // [N,C]
    const int*   batch    = (const int*)d_in[2];     // [N]

    float* out_point = (float*)d_out;                              // [B,3,L]
    float* out_feat  = (float*)d_out + (size_t)BATCH * 3 * LOUT;   // [B,C,L]

    boundary_kernel<<<64, 256>>>(batch);

    // Gather launched as a programmatic dependent of boundary_kernel.
    cudaLaunchConfig_t cfg = {};
    cfg.gridDim  = dim3(PT_BLOCKS + 8192, 1, 1);
    cfg.blockDim = dim3(256, 1, 1);
    cfg.dynamicSmemBytes = 0;
    cfg.stream = 0;
    cudaLaunchAttribute attr[1];
    attr[0].id = cudaLaunchAttributeProgrammaticStreamSerialization;
    attr[0].val.programmaticStreamSerializationAllowed = 1;
    cfg.attrs = attr;
    cfg.numAttrs = 1;
    cudaLaunchKernelEx(&cfg, gather_kernel,
                       points_x, (const float4*)feat, out_point, out_feat);
}

// round 15
// speedup vs baseline: 1.1310x; 1.0066x over previous
#include <cuda_runtime.h>
#include <cuda_bf16.h>

#define NPTS   65536
#define CHN    256
#define BATCH  16
#define LOUT   8192
#define LOG2L  13

// g_off[b] = first index with batch id >= b; g_off[BATCH] = NPTS.
__device__ int g_off[BATCH + 1];

// ------------------------------------------------------- boundary detect ---
// batch sorted; int4 loads, boundary write-out, no atomics. PDL trigger at
// entry so the gather grid launches while this runs.
__global__ void boundary_kernel(const int* __restrict__ batch) {
    asm volatile("griddepcontrol.launch_dependents;");
    int t = blockIdx.x * blockDim.x + threadIdx.x;   // 0 .. NPTS/4-1
    if (t >= NPTS / 4) return;
    int4 v = ((const int4*)batch)[t];
    int prev = (t == 0) ? -1 : __ldg(&batch[4 * t - 1]);
    for (int bb = prev + 1; bb <= v.x; bb++) g_off[bb] = 4 * t + 0;
    for (int bb = v.x + 1;  bb <= v.y; bb++) g_off[bb] = 4 * t + 1;
    for (int bb = v.y + 1;  bb <= v.z; bb++) g_off[bb] = 4 * t + 2;
    for (int bb = v.z + 1;  bb <= v.w; bb++) g_off[bb] = 4 * t + 3;
    if (t == NPTS / 4 - 1)
        for (int bb = v.w + 1; bb <= BATCH; bb++) g_off[bb] = NPTS;
}

// ----------------------------------------------------------- main gather ---
// R14 structure. New: cross-lane D dedup — lane L's D row equals lane L+1's A
// row whenever src(j0+4) == r3 (~50% of lanes at ~2x upsample). Condition is
// pure ALU (r4 computed arithmetically), so A and the predicated D load still
// issue back-to-back; non-loading lanes take D from shfl_down(A,1).
#define PT_BLOCKS 128

__global__ __launch_bounds__(256, 8)
void gather_kernel(const float* __restrict__ px,
                   const float4* __restrict__ feat4,
                   float* __restrict__ out_point,
                   float* __restrict__ out_feat) {
    __shared__ int s_off, s_cnt;
    int bid = blockIdx.x;
    int tid = threadIdx.x;

    if (bid < PT_BLOCKS) {
        int idx = bid * 256 + tid;            // 0..32767
        int b = idx >> 11;
        int j = (idx & 2047) * 4;
        asm volatile("griddepcontrol.wait;");
        if (tid == 0) { s_off = g_off[b]; s_cnt = g_off[b + 1] - g_off[b]; }
        __syncthreads();
        int off = s_off, cnt = s_cnt;
        float4 ox, oy, oz;
        #pragma unroll
        for (int t = 0; t < 4; t++) {
            int src = off + (int)(((unsigned)((j + t) * cnt)) >> LOG2L);
            const float* p = px + 3 * src;
            ((float*)&ox)[t] = p[0];
            ((float*)&oy)[t] = p[1];
            ((float*)&oz)[t] = p[2];
        }
        size_t base = (size_t)b * 3 * LOUT + j;
        __stcs((float4*)(out_point + base),            ox);
        __stcs((float4*)(out_point + base + LOUT),     oy);
        __stcs((float4*)(out_point + base + 2 * LOUT), oz);
        return;
    }

    // ---- features ----
    int idx = (bid - PT_BLOCKS) * 256 + tid;  // 0 .. 2097151
    int jq = idx & 2047;
    int c4 = (idx >> 11) & 63;
    int b  = idx >> 17;                       // block-uniform
    int j0 = jq * 4;
    int L  = tid & 31;                        // lanes = consecutive jq
    asm volatile("griddepcontrol.wait;");
    if (tid == 0) { s_off = g_off[b]; s_cnt = g_off[b + 1] - g_off[b]; }
    __syncthreads();
    int off = s_off, cnt = s_cnt;

    // Monotone source rows; r4 = next quad's first row (ALU only).
    int r0 = off + (int)(((unsigned)((j0 + 0) * cnt)) >> LOG2L);
    int r1 = off + (int)(((unsigned)((j0 + 1) * cnt)) >> LOG2L);
    int r2 = off + (int)(((unsigned)((j0 + 2) * cnt)) >> LOG2L);
    int r3 = off + (int)(((unsigned)((j0 + 3) * cnt)) >> LOG2L);
    int r4 = off + (int)(((unsigned)((j0 + 4) * cnt)) >> LOG2L);

    const float4* fb = feat4 + c4;
    bool needD = (L == 31) || (r4 != r3);

    float4 A = __ldg(fb + (size_t)r0 * (CHN / 4));
    float4 D;
    if (needD) D = __ldg(fb + (size_t)r3 * (CHN / 4));

    // Lanes with r4 == r3 take D from the next lane's A (same row).
    float sx = __shfl_down_sync(0xffffffffu, A.x, 1);
    float sy = __shfl_down_sync(0xffffffffu, A.y, 1);
    float sz = __shfl_down_sync(0xffffffffu, A.z, 1);
    float sw = __shfl_down_sync(0xffffffffu, A.w, 1);
    if (!needD) { D.x = sx; D.y = sy; D.z = sz; D.w = sw; }

    float4 v1 = (r1 == r0) ? A : D;
    if (r1 > r0 && r1 < r3) v1 = __ldg(fb + (size_t)r1 * (CHN / 4));
    float4 v2 = (r2 == r3) ? D : A;
    if (r2 > r0 && r2 < r3) v2 = __ldg(fb + (size_t)r2 * (CHN / 4));

    float* ob = out_feat + ((size_t)b * CHN + 4 * c4) * LOUT + j0;
    float4 o;
    o.x = A.x;  o.y = v1.x; o.z = v2.x; o.w = D.x;
    __stcs((float4*)(ob + 0 * LOUT), o);
    o.x = A.y;  o.y = v1.y; o.z = v2.y; o.w = D.y;
    __stcs((float4*)(ob + 1 * LOUT), o);
    o.x = A.z;  o.y = v1.z; o.z = v2.z; o.w = D.z;
    __stcs((float4*)(ob + 2 * LOUT), o);
    o.x = A.w;  o.y = v1.w; o.z = v2.w; o.w = D.w;
    __stcs((float4*)(ob + 3 * LOUT), o);
}

// ------------------------------------------------------------- launch ------
extern "C" void kernel_launch(void* const* d_in, const int* in_sizes, int n_in,
                              void* d_out, int out_size) {
    const float* points_x = (const float*)d_in[0];   // [N,3]
    const float* feat     = (const float*)d_in[1];   // [N,C]
    const int*   batch    = (const int*)d_in[2];     // [N]

    float* out_point = (float*)d_out;                              // [B,3,L]
    float* out_feat  = (float*)d_out + (size_t)BATCH * 3 * LOUT;   // [B,C,L]

    boundary_kernel<<<64, 256>>>(batch);

    // Gather launched as a programmatic dependent of boundary_kernel.
    cudaLaunchConfig_t cfg = {};
    cfg.gridDim  = dim3(PT_BLOCKS + 8192, 1, 1);
    cfg.blockDim = dim3(256, 1, 1);
    cfg.dynamicSmemBytes = 0;
    cfg.stream = 0;
    cudaLaunchAttribute attr[1];
    attr[0].id = cudaLaunchAttributeProgrammaticStreamSerialization;
    attr[0].val.programmaticStreamSerializationAllowed = 1;
    cfg.attrs = attr;
    cfg.numAttrs = 1;
    cudaLaunchKernelEx(&cfg, gather_kernel,
                       points_x, (const float4*)feat, out_point, out_feat);
}

// round 16
// speedup vs baseline: 1.1989x; 1.0601x over previous
#include <cuda_runtime.h>
#include <cuda_bf16.h>

#define NPTS   65536
#define CHN    256
#define BATCH  16
#define LOUT   8192
#define LOG2L  13

// g_off[b] = first index with batch id >= b; g_off[BATCH] = NPTS.
__device__ int g_off[BATCH + 1];

// ------------------------------------------------------- boundary detect ---
// batch sorted; int4 loads, boundary write-out, no atomics. PDL trigger at
// entry so the gather grid launches while this runs.
__global__ void boundary_kernel(const int* __restrict__ batch) {
    asm volatile("griddepcontrol.launch_dependents;");
    int t = blockIdx.x * blockDim.x + threadIdx.x;   // 0 .. NPTS/4-1
    if (t >= NPTS / 4) return;
    int4 v = ((const int4*)batch)[t];
    int prev = (t == 0) ? -1 : __ldg(&batch[4 * t - 1]);
    for (int bb = prev + 1; bb <= v.x; bb++) g_off[bb] = 4 * t + 0;
    for (int bb = v.x + 1;  bb <= v.y; bb++) g_off[bb] = 4 * t + 1;
    for (int bb = v.y + 1;  bb <= v.z; bb++) g_off[bb] = 4 * t + 2;
    for (int bb = v.z + 1;  bb <= v.w; bb++) g_off[bb] = 4 * t + 3;
    if (t == NPTS / 4 - 1)
        for (int bb = v.w + 1; bb <= BATCH; bb++) g_off[bb] = NPTS;
}

// ----------------------------------------------------------- main gather ---
// R15 body + lane-pairing remap: lane pair (2k,2k+1) covers the SAME jq with
// adjacent channel-quads c4base/c4base+1 -> every LDG.128's lane pairs share
// one 128B line (load wavefronts and L2 read sectors halve). Stores: even/odd
// lanes write two 256B-contiguous chunks per STG.128 (same 16 sectors as the
// single-512B pattern). Shfl-dedup neighbor is lane L+2 (same parity/c4).
#define PT_BLOCKS 128

__global__ __launch_bounds__(256, 8)
void gather_kernel(const float* __restrict__ px,
                   const float4* __restrict__ feat4,
                   float* __restrict__ out_point,
                   float* __restrict__ out_feat) {
    __shared__ int s_off, s_cnt;
    int bid = blockIdx.x;
    int tid = threadIdx.x;

    if (bid < PT_BLOCKS) {
        int idx = bid * 256 + tid;            // 0..32767
        int b = idx >> 11;
        int j = (idx & 2047) * 4;
        asm volatile("griddepcontrol.wait;");
        if (tid == 0) { s_off = g_off[b]; s_cnt = g_off[b + 1] - g_off[b]; }
        __syncthreads();
        int off = s_off, cnt = s_cnt;
        float4 ox, oy, oz;
        #pragma unroll
        for (int t = 0; t < 4; t++) {
            int src = off + (int)(((unsigned)((j + t) * cnt)) >> LOG2L);
            const float* p = px + 3 * src;
            ((float*)&ox)[t] = p[0];
            ((float*)&oy)[t] = p[1];
            ((float*)&oz)[t] = p[2];
        }
        size_t base = (size_t)b * 3 * LOUT + j;
        __stcs((float4*)(out_point + base),            ox);
        __stcs((float4*)(out_point + base + LOUT),     oy);
        __stcs((float4*)(out_point + base + 2 * LOUT), oz);
        return;
    }

    // ---- features ----
    // Block = (b, jq-block of 128, c4-pair). Warp covers 16 jq x 2 c4.
    int fb    = bid - PT_BLOCKS;              // 0..8191
    int c4p   = fb & 31;                      // 32 channel-quad pairs
    int jqblk = (fb >> 5) & 15;               // 16 jq-blocks of 128
    int b     = fb >> 9;                      // block-uniform
    int w = tid >> 5, L = tid & 31;
    int p = L >> 1, par = L & 1;
    asm volatile("griddepcontrol.wait;");
    if (tid == 0) { s_off = g_off[b]; s_cnt = g_off[b + 1] - g_off[b]; }
    __syncthreads();
    int off = s_off, cnt = s_cnt;

    int jq = jqblk * 128 + w * 16 + p;        // 0..2047
    int c4 = c4p * 2 + par;                   // 0..63
    int j0 = jq * 4;

    // Monotone source rows; r4 = next quad's first row (ALU only).
    int r0 = off + (int)(((unsigned)((j0 + 0) * cnt)) >> LOG2L);
    int r1 = off + (int)(((unsigned)((j0 + 1) * cnt)) >> LOG2L);
    int r2 = off + (int)(((unsigned)((j0 + 2) * cnt)) >> LOG2L);
    int r3 = off + (int)(((unsigned)((j0 + 3) * cnt)) >> LOG2L);
    int r4 = off + (int)(((unsigned)((j0 + 4) * cnt)) >> LOG2L);

    const float4* fbp = feat4 + c4;
    bool needD = (p == 15) || (r4 != r3);

    float4 A = __ldg(fbp + (size_t)r0 * (CHN / 4));
    float4 D;
    if (needD) D = __ldg(fbp + (size_t)r3 * (CHN / 4));

    // Lanes with r4 == r3 take D from lane L+2's A (same row, same c4).
    float sx = __shfl_down_sync(0xffffffffu, A.x, 2);
    float sy = __shfl_down_sync(0xffffffffu, A.y, 2);
    float sz = __shfl_down_sync(0xffffffffu, A.z, 2);
    float sw = __shfl_down_sync(0xffffffffu, A.w, 2);
    if (!needD) { D.x = sx; D.y = sy; D.z = sz; D.w = sw; }

    float4 v1 = (r1 == r0) ? A : D;
    if (r1 > r0 && r1 < r3) v1 = __ldg(fbp + (size_t)r1 * (CHN / 4));
    float4 v2 = (r2 == r3) ? D : A;
    if (r2 > r0 && r2 < r3) v2 = __ldg(fbp + (size_t)r2 * (CHN / 4));

    float* ob = out_feat + ((size_t)b * CHN + 4 * c4) * LOUT + j0;
    float4 o;
    o.x = A.x;  o.y = v1.x; o.z = v2.x; o.w = D.x;
    __stcs((float4*)(ob + 0 * LOUT), o);
    o.x = A.y;  o.y = v1.y; o.z = v2.y; o.w = D.y;
    __stcs((float4*)(ob + 1 * LOUT), o);
    o.x = A.z;  o.y = v1.z; o.z = v2.z; o.w = D.z;
    __stcs((float4*)(ob + 2 * LOUT), o);
    o.x = A.w;  o.y = v1.w; o.z = v2.w; o.w = D.w;
    __stcs((float4*)(ob + 3 * LOUT), o);
}

// ------------------------------------------------------------- launch ------
extern "C" void kernel_launch(void* const* d_in, const int* in_sizes, int n_in,
                              void* d_out, int out_size) {
    const float* points_x = (const float*)d_in[0];   // [N,3]
    const float* feat     = (const float*)d_in[1];   // [N,C]
    const int*   batch    = (const int*)d_in[2];     // [N]

    float* out_point = (float*)d_out;                              // [B,3,L]
    float* out_feat  = (float*)d_out + (size_t)BATCH * 3 * LOUT;   // [B,C,L]

    boundary_kernel<<<64, 256>>>(batch);

    // Gather launched as a programmatic dependent of boundary_kernel.
    cudaLaunchConfig_t cfg = {};
    cfg.gridDim  = dim3(PT_BLOCKS + 8192, 1, 1);
    cfg.blockDim = dim3(256, 1, 1);
    cfg.dynamicSmemBytes = 0;
    cfg.stream = 0;
    cudaLaunchAttribute attr[1];
    attr[0].id = cudaLaunchAttributeProgrammaticStreamSerialization;
    attr[0].val.programmaticStreamSerializationAllowed = 1;
    cfg.attrs = attr;
    cfg.numAttrs = 1;
    cudaLaunchKernelEx(&cfg, gather_kernel,
                       points_x, (const float4*)feat, out_point, out_feat);
}

// round 17
// speedup vs baseline: 1.2395x; 1.0339x over previous
#include <cuda_runtime.h>
#include <cuda_bf16.h>

#define NPTS   65536
#define CHN    256
#define BATCH  16
#define LOUT   8192
#define LOG2L  13

// g_off[b] = first index with batch id >= b; g_off[BATCH] = NPTS.
__device__ int g_off[BATCH + 1];

// ------------------------------------------------------- boundary detect ---
// batch sorted; int4 loads, boundary write-out, no atomics. PDL trigger at
// entry so the gather grid launches while this runs.
__global__ void boundary_kernel(const int* __restrict__ batch) {
    asm volatile("griddepcontrol.launch_dependents;");
    int t = blockIdx.x * blockDim.x + threadIdx.x;   // 0 .. NPTS/4-1
    if (t >= NPTS / 4) return;
    int4 v = ((const int4*)batch)[t];
    int prev = (t == 0) ? -1 : __ldg(&batch[4 * t - 1]);
    for (int bb = prev + 1; bb <= v.x; bb++) g_off[bb] = 4 * t + 0;
    for (int bb = v.x + 1;  bb <= v.y; bb++) g_off[bb] = 4 * t + 1;
    for (int bb = v.y + 1;  bb <= v.z; bb++) g_off[bb] = 4 * t + 2;
    for (int bb = v.z + 1;  bb <= v.w; bb++) g_off[bb] = 4 * t + 3;
    if (t == NPTS / 4 - 1)
        for (int bb = v.w + 1; bb <= BATCH; bb++) g_off[bb] = NPTS;
}

// ----------------------------------------------------------- main gather ---
// R16 body with quad lane-grouping: lane group (L&3 = adjacent c4, L>>2 = jq)
// reads 64B contiguous per load group -> 8 distinct lines per LDG.128 (was
// 16 with pairs). Stores: per STG.128, equal-(L&3) lanes write 8 consecutive
// j-quads = 128B contiguous chunk; 4 chunks = 4 lines/instr (same as pairs;
// 8-wide grouping would drop chunks to 64B -> regression per R6, so stop at 4).
// Shfl-dedup neighbor = lane L+4 (same c4, next jq).
#define PT_BLOCKS 128

__global__ __launch_bounds__(256, 8)
void gather_kernel(const float* __restrict__ px,
                   const float4* __restrict__ feat4,
                   float* __restrict__ out_point,
                   float* __restrict__ out_feat) {
    __shared__ int s_off, s_cnt;
    int bid = blockIdx.x;
    int tid = threadIdx.x;

    if (bid < PT_BLOCKS) {
        int idx = bid * 256 + tid;            // 0..32767
        int b = idx >> 11;
        int j = (idx & 2047) * 4;
        asm volatile("griddepcontrol.wait;");
        if (tid == 0) { s_off = g_off[b]; s_cnt = g_off[b + 1] - g_off[b]; }
        __syncthreads();
        int off = s_off, cnt = s_cnt;
        float4 ox, oy, oz;
        #pragma unroll
        for (int t = 0; t < 4; t++) {
            int src = off + (int)(((unsigned)((j + t) * cnt)) >> LOG2L);
            const float* p = px + 3 * src;
            ((float*)&ox)[t] = p[0];
            ((float*)&oy)[t] = p[1];
            ((float*)&oz)[t] = p[2];
        }
        size_t base = (size_t)b * 3 * LOUT + j;
        __stcs((float4*)(out_point + base),            ox);
        __stcs((float4*)(out_point + base + LOUT),     oy);
        __stcs((float4*)(out_point + base + 2 * LOUT), oz);
        return;
    }

    // ---- features ----
    // Block = (b, jq-block of 64, c4-group of 4). Warp covers 8 jq x 4 c4.
    int fb    = bid - PT_BLOCKS;              // 0..8191
    int c4g   = fb & 15;                      // 16 channel-quad groups of 4
    int jqblk = (fb >> 4) & 31;               // 32 jq-blocks of 64
    int b     = fb >> 9;                      // block-uniform
    int w = tid >> 5, L = tid & 31;
    int p = L >> 2, cl = L & 3;
    asm volatile("griddepcontrol.wait;");
    if (tid == 0) { s_off = g_off[b]; s_cnt = g_off[b + 1] - g_off[b]; }
    __syncthreads();
    int off = s_off, cnt = s_cnt;

    int jq = jqblk * 64 + w * 8 + p;          // 0..2047
    int c4 = c4g * 4 + cl;                    // 0..63
    int j0 = jq * 4;

    // Monotone source rows; r4 = next quad's first row (ALU only).
    int r0 = off + (int)(((unsigned)((j0 + 0) * cnt)) >> LOG2L);
    int r1 = off + (int)(((unsigned)((j0 + 1) * cnt)) >> LOG2L);
    int r2 = off + (int)(((unsigned)((j0 + 2) * cnt)) >> LOG2L);
    int r3 = off + (int)(((unsigned)((j0 + 3) * cnt)) >> LOG2L);
    int r4 = off + (int)(((unsigned)((j0 + 4) * cnt)) >> LOG2L);

    const float4* fbp = feat4 + c4;
    bool needD = (p == 7) || (r4 != r3);

    float4 A = __ldg(fbp + (size_t)r0 * (CHN / 4));
    float4 D;
    if (needD) D = __ldg(fbp + (size_t)r3 * (CHN / 4));

    // Lanes with r4 == r3 take D from lane L+4's A (same row, same c4).
    float sx = __shfl_down_sync(0xffffffffu, A.x, 4);
    float sy = __shfl_down_sync(0xffffffffu, A.y, 4);
    float sz = __shfl_down_sync(0xffffffffu, A.z, 4);
    float sw = __shfl_down_sync(0xffffffffu, A.w, 4);
    if (!needD) { D.x = sx; D.y = sy; D.z = sz; D.w = sw; }

    float4 v1 = (r1 == r0) ? A : D;
    if (r1 > r0 && r1 < r3) v1 = __ldg(fbp + (size_t)r1 * (CHN / 4));
    float4 v2 = (r2 == r3) ? D : A;
    if (r2 > r0 && r2 < r3) v2 = __ldg(fbp + (size_t)r2 * (CHN / 4));

    float* ob = out_feat + ((size_t)b * CHN + 4 * c4) * LOUT + j0;
    float4 o;
    o.x = A.x;  o.y = v1.x; o.z = v2.x; o.w = D.x;
    __stcs((float4*)(ob + 0 * LOUT), o);
    o.x = A.y;  o.y = v1.y; o.z = v2.y; o.w = D.y;
    __stcs((float4*)(ob + 1 * LOUT), o);
    o.x = A.z;  o.y = v1.z; o.z = v2.z; o.w = D.z;
    __stcs((float4*)(ob + 2 * LOUT), o);
    o.x = A.w;  o.y = v1.w; o.z = v2.w; o.w = D.w;
    __stcs((float4*)(ob + 3 * LOUT), o);
}

// ------------------------------------------------------------- launch ------
extern "C" void kernel_launch(void* const* d_in, const int* in_sizes, int n_in,
                              void* d_out, int out_size) {
    const float* points_x = (const float*)d_in[0];   // [N,3]
    const float* feat     = (const float*)d_in[1];   // [N,C]
    const int*   batch    = (const int*)d_in[2];     // [N]

    float* out_point = (float*)d_out;                              // [B,3,L]
    float* out_feat  = (float*)d_out + (size_t)BATCH * 3 * LOUT;   // [B,C,L]

    boundary_kernel<<<64, 256>>>(batch);

    // Gather launched as a programmatic dependent of boundary_kernel.
    cudaLaunchConfig_t cfg = {};
    cfg.gridDim  = dim3(PT_BLOCKS + 8192, 1, 1);
    cfg.blockDim = dim3(256, 1, 1);
    cfg.dynamicSmemBytes = 0;
    cfg.stream = 0;
    cudaLaunchAttribute attr[1];
    attr[0].id = cudaLaunchAttributeProgrammaticStreamSerialization;
    attr[0].val.programmaticStreamSerializationAllowed = 1;
    cfg.attrs = attr;
    cfg.numAttrs = 1;
    cudaLaunchKernelEx(&cfg, gather_kernel,
                       points_x, (const float4*)feat, out_point, out_feat);
}